// round 17
// baseline (speedup 1.0000x reference)
#include <cuda_runtime.h>

// InfoEnlargeEmbedding: out[b,l,:] = concat(x[b,l,:], x[b,idxs[b,0],:], x[b,idxs[b,1],:])
// B=64, L=1024, D=256, K=2.
// R17: R6 structure at R=4 (finer tail granularity, higher occupancy).
//   - 192 threads/block, 4 output rows per block.
//   - Copy lanes (c<64): 4 independent LDG.128 front-batched, then 4 STG.128.
//   - Gather lanes: 1 L2-hit LDG.128 broadcast-stored to 4 rows.
// Fallback/best-so-far: R6 (R=8) at 45.28us dur / 40.19us kernel.

static constexpr int B = 64;
static constexpr int L = 1024;
static constexpr int D4 = 64;               // float4 per source row
static constexpr int K = 2;
static constexpr int OUT4 = D4 * (1 + K);   // 192 float4 per output row
static constexpr int R = 4;                 // rows (bl) per block

__global__ void __launch_bounds__(OUT4)
info_enlarge_kernel(const float4* __restrict__ x,
                    const int* __restrict__ idxs,
                    float4* __restrict__ out) {
    const int row0 = blockIdx.x * R;        // base bl; all R rows share b
    const int b    = row0 >> 10;            // / L
    const int c    = threadIdx.x;           // 0..191

    if (c < D4) {
        // Straight copy region: 4 independent loads, then 4 stores.
        float4 v[R];
        #pragma unroll
        for (int u = 0; u < R; u++)
            v[u] = x[(size_t)(row0 + u) * D4 + c];
        #pragma unroll
        for (int u = 0; u < R; u++)
            out[(size_t)(row0 + u) * OUT4 + c] = v[u];
    } else {
        // Gather region: same source row for all 4 output rows.
        const int kd = c - D4;
        const int k  = kd >> 6;             // / D4
        const int dd = kd & (D4 - 1);
        const int li = __ldg(idxs + b * K + k);
        const float4 v = __ldg(x + ((size_t)b * L + li) * D4 + dd);
        #pragma unroll
        for (int u = 0; u < R; u++)
            out[(size_t)(row0 + u) * OUT4 + c] = v;
    }
}

extern "C" void kernel_launch(void* const* d_in, const int* in_sizes, int n_in,
                              void* d_out, int out_size) {
    const float4* x  = (const float4*)d_in[0];
    const int* idxs  = (const int*)d_in[1];
    float4* out      = (float4*)d_out;

    info_enlarge_kernel<<<(B * L) / R, OUT4>>>(x, idxs, out);
}